// round 2
// baseline (speedup 1.0000x reference)
#include <cuda_runtime.h>
#include <cstdint>

#define B_    16
#define FIN_  16
#define FOUT_ 16
#define H_    384
#define W_    384
#define LAT_  512
#define NMIX_ 8
#define HW_   (H_ * W_)        // 147456
#define PLANE4_ (HW_ / 4)      // 36864 float4 groups per channel plane

// Scratch: per-sample kernel packed as {k,k} in a 64-bit word (f32x2 operand),
// and bias likewise. __device__ globals per the no-allocation rule.
__device__ unsigned long long g_k2[B_ * FOUT_ * FIN_];   // 4096 * 8B = 32 KB
__device__ unsigned long long g_b2[B_ * FOUT_];          // 256 * 8B

__device__ __forceinline__ unsigned long long pack2(float v) {
    unsigned int u = __float_as_uint(v);
    return ((unsigned long long)u << 32) | (unsigned long long)u;
}

__device__ __forceinline__ unsigned long long ffma2(unsigned long long a,
                                                    unsigned long long b,
                                                    unsigned long long c) {
    unsigned long long d;
    asm("fma.rn.f32x2 %0, %1, %2, %3;" : "=l"(d) : "l"(a), "l"(b), "l"(c));
    return d;
}

// ---------------------------------------------------------------------------
// Kernel A: build mix[b,m], then per-sample K[b,o,i] and bias[b,o], packed.
// One block of 256 threads; total work is tiny (~100k FLOP + 48 KB reads).
// ---------------------------------------------------------------------------
__global__ void mixconv_prep(const float* __restrict__ lat,
                             const float* __restrict__ kernel_mix,
                             const float* __restrict__ bias_mix,
                             const float* __restrict__ w_dyn,
                             const float* __restrict__ b_dyn) {
    __shared__ float s_mix[B_ * NMIX_];   // 128
    int t = threadIdx.x;

    if (t < B_ * NMIX_) {
        int b = t / NMIX_;
        int m = t % NMIX_;
        const float* lp = lat + b * LAT_;
        const float* wp = w_dyn + m * LAT_;
        float s = b_dyn[m];
        #pragma unroll 8
        for (int j = 0; j < LAT_; ++j) s = fmaf(lp[j], wp[j], s);
        s_mix[t] = s;
    }
    __syncthreads();

    // kernel: 4096 entries, 16 per thread
    for (int e = t; e < B_ * FOUT_ * FIN_; e += 256) {
        int b  = e >> 8;            // /256
        int oi = e & 255;           // o*16+i
        float s = 0.f;
        #pragma unroll
        for (int m = 0; m < NMIX_; ++m)
            s = fmaf(s_mix[b * NMIX_ + m], kernel_mix[m * (FOUT_ * FIN_) + oi], s);
        g_k2[e] = pack2(s);
    }
    // bias: 256 entries, 1 per thread
    if (t < B_ * FOUT_) {
        int b = t / FOUT_;
        int o = t % FOUT_;
        float s = 0.f;
        #pragma unroll
        for (int m = 0; m < NMIX_; ++m)
            s = fmaf(s_mix[b * NMIX_ + m], bias_mix[m * FOUT_ + o], s);
        g_b2[t] = pack2(s);
    }
}

// ---------------------------------------------------------------------------
// Kernel B: the streaming conv. grid = (PLANE4_/256, B_), block = 256.
// Each thread: one float4 pixel group; 16 LDG.128 in, 512 fma.f32x2, 16 STG.128.
// ---------------------------------------------------------------------------
__global__ void __launch_bounds__(256, 2)
mixconv_main(const float* __restrict__ x, float* __restrict__ out) {
    __shared__ unsigned long long sk[FOUT_ * FIN_];  // packed {k,k}
    __shared__ unsigned long long sb[FOUT_];

    const int b = blockIdx.y;
    const int t = threadIdx.x;

    sk[t] = g_k2[b * (FOUT_ * FIN_) + t];           // 256 threads, 256 entries
    if (t < FOUT_) sb[t] = g_b2[b * FOUT_ + t];
    __syncthreads();

    const int p = blockIdx.x * 256 + t;             // float4 group in plane

    const ulonglong2* __restrict__ xp =
        (const ulonglong2*)(x + (size_t)b * FIN_ * HW_);
    ulonglong2* __restrict__ op =
        (ulonglong2*)(out + (size_t)b * FOUT_ * HW_);

    unsigned long long in_lo[FIN_], in_hi[FIN_];
    #pragma unroll
    for (int i = 0; i < FIN_; ++i) {
        ulonglong2 v = xp[(size_t)i * PLANE4_ + p];
        in_lo[i] = v.x;
        in_hi[i] = v.y;
    }

    #pragma unroll
    for (int o = 0; o < FOUT_; ++o) {
        unsigned long long alo = sb[o];
        unsigned long long ahi = alo;
        #pragma unroll
        for (int i = 0; i < FIN_; ++i) {
            unsigned long long k = sk[o * FIN_ + i];   // warp-uniform broadcast LDS.64
            alo = ffma2(k, in_lo[i], alo);
            ahi = ffma2(k, in_hi[i], ahi);
        }
        ulonglong2 r;
        r.x = alo;
        r.y = ahi;
        op[(size_t)o * PLANE4_ + p] = r;
    }
}

// ---------------------------------------------------------------------------
extern "C" void kernel_launch(void* const* d_in, const int* in_sizes, int n_in,
                              void* d_out, int out_size) {
    const float* x          = (const float*)d_in[0];  // [16,16,384,384]
    const float* lat        = (const float*)d_in[1];  // [16,512]
    const float* kernel_mix = (const float*)d_in[2];  // [8,16,16]
    const float* bias_mix   = (const float*)d_in[3];  // [8,16]
    const float* w_dyn      = (const float*)d_in[4];  // [8,512]
    const float* b_dyn      = (const float*)d_in[5];  // [8]
    float* out = (float*)d_out;

    mixconv_prep<<<1, 256>>>(lat, kernel_mix, bias_mix, w_dyn, b_dyn);

    dim3 grid(PLANE4_ / 256, B_);   // (144, 16) = 2304 blocks
    mixconv_main<<<grid, 256>>>(x, out);
}

// round 4
// speedup vs baseline: 1.2635x; 1.2635x over previous
#include <cuda_runtime.h>
#include <cstdint>

#define B_    16
#define FIN_  16
#define FOUT_ 16
#define H_    384
#define W_    384
#define LAT_  512
#define NMIX_ 8
#define HW_   (H_ * W_)          // 147456
#define PLANE2_ (HW_ / 2)        // 73728 float2 groups per channel plane

__device__ __forceinline__ unsigned long long pack2(float v) {
    unsigned int u = __float_as_uint(v);
    return ((unsigned long long)u << 32) | (unsigned long long)u;
}

__device__ __forceinline__ unsigned long long ffma2(unsigned long long a,
                                                    unsigned long long b,
                                                    unsigned long long c) {
    unsigned long long d;
    asm("fma.rn.f32x2 %0, %1, %2, %3;" : "=l"(d) : "l"(a), "l"(b), "l"(c));
    return d;
}

// ---------------------------------------------------------------------------
// Single fused kernel.
//   Phase 1 (per block, ~1us, L2-resident after wave 1): warp m computes
//     mix[b][m] = dot(lat[b], w_dyn[m]) + b_dyn[m]   (warp-parallel + shfl)
//   then 256 threads combine the 16x16 per-sample kernel + bias into smem,
//   packed {k,k} for fma.rn.f32x2.
//   Phase 2: streaming conv. Each thread owns one float2 pixel group:
//     16 LDG.64 in, 256 ffma2, 16 STG.64 out. 32 input regs -> 4 CTAs/SM.
// ---------------------------------------------------------------------------
__global__ void __launch_bounds__(256, 4)
mixconv_fused(const float* __restrict__ x,
              const float* __restrict__ lat,
              const float* __restrict__ kernel_mix,
              const float* __restrict__ bias_mix,
              const float* __restrict__ w_dyn,
              const float* __restrict__ b_dyn,
              float* __restrict__ out) {
    __shared__ float s_mix[NMIX_];
    __shared__ unsigned long long sk[FOUT_ * FIN_];   // packed {k,k}
    __shared__ unsigned long long sb[FOUT_];

    const int b    = blockIdx.y;
    const int t    = threadIdx.x;
    const int w    = t >> 5;      // warp id 0..7  == mixture index
    const int lane = t & 31;

    // ---- Phase 1a: mix[b][w] via warp-parallel dot product -------------
    {
        const float* __restrict__ lp = lat + b * LAT_;
        const float* __restrict__ wp = w_dyn + w * LAT_;
        float s = 0.f;
        #pragma unroll
        for (int j = 0; j < LAT_ / 32; ++j)
            s = fmaf(__ldg(lp + lane + 32 * j), __ldg(wp + lane + 32 * j), s);
        #pragma unroll
        for (int off = 16; off > 0; off >>= 1)
            s += __shfl_xor_sync(0xffffffffu, s, off);
        if (lane == 0) s_mix[w] = s + __ldg(b_dyn + w);
    }
    __syncthreads();

    // ---- Phase 1b: per-sample kernel + bias into smem ------------------
    {
        float s = 0.f;
        #pragma unroll
        for (int m = 0; m < NMIX_; ++m)
            s = fmaf(s_mix[m], __ldg(kernel_mix + m * (FOUT_ * FIN_) + t), s);
        sk[t] = pack2(s);
        if (t < FOUT_) {
            float sv = 0.f;
            #pragma unroll
            for (int m = 0; m < NMIX_; ++m)
                sv = fmaf(s_mix[m], __ldg(bias_mix + m * FOUT_ + t), sv);
            sb[t] = pack2(sv);
        }
    }
    __syncthreads();

    // ---- Phase 2: streaming conv over one float2 group -----------------
    const int p = blockIdx.x * 256 + t;

    const unsigned long long* __restrict__ xp =
        (const unsigned long long*)(x + (size_t)b * FIN_ * HW_);
    unsigned long long* __restrict__ op =
        (unsigned long long*)(out + (size_t)b * FOUT_ * HW_);

    unsigned long long in[FIN_];
    #pragma unroll
    for (int i = 0; i < FIN_; ++i)
        in[i] = __ldcs(xp + (size_t)i * PLANE2_ + p);

    #pragma unroll
    for (int o = 0; o < FOUT_; ++o) {
        unsigned long long a = sb[o];
        #pragma unroll
        for (int i = 0; i < FIN_; ++i)
            a = ffma2(sk[o * FIN_ + i], in[i], a);   // uniform LDS.64 broadcast
        __stcs(op + (size_t)o * PLANE2_ + p, a);
    }
}

// ---------------------------------------------------------------------------
extern "C" void kernel_launch(void* const* d_in, const int* in_sizes, int n_in,
                              void* d_out, int out_size) {
    const float* x          = (const float*)d_in[0];  // [16,16,384,384]
    const float* lat        = (const float*)d_in[1];  // [16,512]
    const float* kernel_mix = (const float*)d_in[2];  // [8,16,16]
    const float* bias_mix   = (const float*)d_in[3];  // [8,16]
    const float* w_dyn      = (const float*)d_in[4];  // [8,512]
    const float* b_dyn      = (const float*)d_in[5];  // [8]
    float* out = (float*)d_out;

    dim3 grid(PLANE2_ / 256, B_);   // (288, 16) = 4608 blocks
    mixconv_fused<<<grid, 256>>>(x, lat, kernel_mix, bias_mix, w_dyn, b_dyn, out);
}